// round 6
// baseline (speedup 1.0000x reference)
#include <cuda_runtime.h>
#include <math.h>
#include <stdint.h>

// Problem constants
#define BB   128
#define NN   256
#define DIN  128
#define HH   8
#define DK   16
#define HK   128            // H*DK
#define ROWS (BB*NN)        // 32768
#define NORMC 0.25f         // 1/sqrt(16)
#define AS   132            // smem row stride for GEMM A tile
#define KVS  68             // K/V smem row stride (multiple of 4 => float4-safe)

// ---------------- device-global scratch ----------------
__device__ float g_Q[(size_t)ROWS * HK];
__device__ float g_K[(size_t)ROWS * HK];
__device__ float g_V[(size_t)ROWS * HK];
__device__ float g_heads[(size_t)ROWS * HK];

// PWL table for the edge MLP (interleaved slope/inter pairs)
__device__ float g_breaks[512];
__device__ float g_tab[512 * 16];
__device__ unsigned short g_seg[(size_t)BB * NN * NN]; // seg | mask<<15

// =====================================================================
// PWL build (one block, 512 threads)
// =====================================================================
__global__ void pwl_build_kernel(const float* __restrict__ mw1, const float* __restrict__ mb1,
                                 const float* __restrict__ mw2, const float* __restrict__ mb2,
                                 const float* __restrict__ mw3, const float* __restrict__ mb3)
{
    __shared__ float w1[16], b1[16], w2[256], b2[16], w3[128], b3[8];
    __shared__ float tsort[16];
    __shared__ float cand[512];
    __shared__ int   cnt;

    const int tid = threadIdx.x;
    if (tid < 16)  { w1[tid] = mw1[tid]; b1[tid] = mb1[tid]; b2[tid] = mb2[tid]; }
    if (tid < 256) w2[tid] = mw2[tid];
    if (tid < 128) w3[tid] = mw3[tid];
    if (tid < 8)   b3[tid] = mb3[tid];
    cand[tid] = 3.0e38f;
    if (tid == 0) cnt = 16;
    __syncthreads();

    if (tid < 16) {
        float t = (w1[tid] != 0.f) ? (-b1[tid] / w1[tid]) : 3.0e38f;
        cand[tid] = t;
    }
    __syncthreads();
    if (tid == 0) {
        for (int i = 0; i < 16; i++) tsort[i] = cand[i];
        for (int i = 1; i < 16; i++) {
            float v = tsort[i]; int k = i - 1;
            while (k >= 0 && tsort[k] > v) { tsort[k + 1] = tsort[k]; k--; }
            tsort[k + 1] = v;
        }
    }
    __syncthreads();

    if (tid < 17 * 16) {
        int iv = tid >> 4, c = tid & 15;
        float lo = (iv == 0)  ? -3.0e38f : tsort[iv - 1];
        float hi = (iv == 16) ?  3.0e38f : tsort[iv];
        if (lo < hi) {
            float m;
            if (lo <= -1e30f && hi >= 1e30f) m = 0.f;
            else if (lo <= -1e30f)           m = hi - 1.f;
            else if (hi >=  1e30f)           m = lo + 1.f;
            else                             m = 0.5f * (lo + hi);
            float g = 0.f, q = b2[c];
            for (int n = 0; n < 16; n++) {
                if (fmaf(m, w1[n], b1[n]) > 0.f) {
                    g = fmaf(w1[n], w2[n * 16 + c], g);
                    q = fmaf(b1[n], w2[n * 16 + c], q);
                }
            }
            if (g != 0.f) {
                float x = -q / g;
                if (x > lo && x < hi && fabsf(x) < 1e30f) {
                    int k = atomicAdd(&cnt, 1);
                    cand[k] = x;
                }
            }
        }
    }
    __syncthreads();
    const int ncand = cnt;

    for (int k = 2; k <= 512; k <<= 1) {
        for (int j = k >> 1; j > 0; j >>= 1) {
            int ixj = tid ^ j;
            if (ixj > tid) {
                bool up = (tid & k) == 0;
                float a = cand[tid], b = cand[ixj];
                if ((a > b) == up) { cand[tid] = b; cand[ixj] = a; }
            }
            __syncthreads();
        }
    }

    g_breaks[tid] = (tid < ncand) ? cand[tid] : 3.0e38f;

    if (tid <= ncand) {
        float lo = (tid == 0)     ? -3.0e38f : cand[tid - 1];
        float hi = (tid == ncand) ?  3.0e38f : cand[tid];
        float m;
        if (lo <= -1e30f && hi >= 1e30f) m = 0.f;
        else if (lo <= -1e30f)           m = hi - 1.f;
        else if (hi >=  1e30f)           m = lo + 1.f;
        else                             m = 0.5f * (lo + hi);

        float slope[8], inter[8];
        for (int h = 0; h < 8; h++) { slope[h] = 0.f; inter[h] = b3[h]; }
        for (int c = 0; c < 16; c++) {
            float gc = 0.f, qc = b2[c];
            for (int n = 0; n < 16; n++) {
                if (fmaf(m, w1[n], b1[n]) > 0.f) {
                    gc = fmaf(w1[n], w2[n * 16 + c], gc);
                    qc = fmaf(b1[n], w2[n * 16 + c], qc);
                }
            }
            if (fmaf(gc, m, qc) > 0.f) {
                for (int h = 0; h < 8; h++) {
                    slope[h] = fmaf(gc, w3[c * 8 + h], slope[h]);
                    inter[h] = fmaf(qc, w3[c * 8 + h], inter[h]);
                }
            }
        }
        for (int h = 0; h < 8; h++) {
            g_tab[tid * 16 + h * 2]     = slope[h];
            g_tab[tid * 16 + h * 2 + 1] = inter[h];
        }
    }
}

// =====================================================================
// seg kernel: per (b,i,j) binary-search segment; fold mask into bit 15
// =====================================================================
__global__ void __launch_bounds__(512) seg_kernel(const float* __restrict__ Ebm,
                                                  const int* __restrict__ mask)
{
    __shared__ float sB[512];
    const int tid = threadIdx.x;
    sB[tid] = g_breaks[tid];
    __syncthreads();

    const size_t v = (size_t)blockIdx.x * 512 + tid;
    float4 e4 = ((const float4*)Ebm)[v];
    int4   m4 = ((const int4*)mask)[v];
    ushort4 out;
    const float ev[4] = {e4.x, e4.y, e4.z, e4.w};
    const int   mv[4] = {m4.x, m4.y, m4.z, m4.w};
    unsigned short ov[4];
#pragma unroll
    for (int p = 0; p < 4; p++) {
        float e = ev[p];
        int seg = 0;
#pragma unroll
        for (int st = 256; st >= 1; st >>= 1) {
            int cnd = seg + st;
            if (e >= sB[cnd - 1]) seg = cnd;
        }
        ov[p] = (unsigned short)(seg | (mv[p] ? 0x8000 : 0));
    }
    out.x = ov[0]; out.y = ov[1]; out.z = ov[2]; out.w = ov[3];
    ((ushort4*)g_seg)[v] = out;
}

// =====================================================================
// GEMM body (as R4)
// =====================================================================
__device__ __forceinline__ void gemm_body(const float* __restrict__ A,
                                          const float* __restrict__ Wraw,
                                          float* __restrict__ Out,
                                          int mode, int row0)
{
    extern __shared__ float sm[];
    float* Wsm = sm;
    float* Asm = sm + 128 * 128;

    const int tid = threadIdx.x;

    for (int i4 = tid; i4 < 4096; i4 += 256) {
        int d = i4 >> 5, c4 = (i4 & 31) * 4;
        float4 w;
        if (mode == 0) w = *(const float4*)(Wraw + (c4 >> 4) * (DIN * 16) + d * 16 + (c4 & 15));
        else           w = *(const float4*)(Wraw + d * 128 + c4);
        *(float4*)(Wsm + d * 128 + c4) = w;
    }
    for (int i4 = tid; i4 < 2048; i4 += 256) {
        int r = i4 >> 5, c4 = (i4 & 31) * 4;
        *(float4*)(Asm + r * AS + c4) = *(const float4*)(A + (size_t)(row0 + r) * 128 + c4);
    }
    __syncthreads();

    const int tx = tid & 15, ty = tid >> 4;
    const int ca = tx * 4;
    const int r0 = ty * 4;
    float acc[4][8];
#pragma unroll
    for (int u = 0; u < 4; u++)
#pragma unroll
        for (int k = 0; k < 8; k++) acc[u][k] = 0.f;

#pragma unroll 2
    for (int dc = 0; dc < 128; dc += 4) {
        float4 a4[4];
#pragma unroll
        for (int u = 0; u < 4; u++) a4[u] = *(const float4*)(Asm + (r0 + u) * AS + dc);
#pragma unroll
        for (int dd = 0; dd < 4; dd++) {
            float4 w0 = *(const float4*)(Wsm + (dc + dd) * 128 + ca);
            float4 w1 = *(const float4*)(Wsm + (dc + dd) * 128 + 64 + ca);
            float wv[8] = {w0.x, w0.y, w0.z, w0.w, w1.x, w1.y, w1.z, w1.w};
#pragma unroll
            for (int u = 0; u < 4; u++) {
                float a = (dd == 0) ? a4[u].x : (dd == 1) ? a4[u].y : (dd == 2) ? a4[u].z : a4[u].w;
#pragma unroll
                for (int k = 0; k < 8; k++) acc[u][k] = fmaf(a, wv[k], acc[u][k]);
            }
        }
    }
#pragma unroll
    for (int u = 0; u < 4; u++) {
        float4 o0 = {acc[u][0], acc[u][1], acc[u][2], acc[u][3]};
        float4 o1 = {acc[u][4], acc[u][5], acc[u][6], acc[u][7]};
        float* orow = Out + (size_t)(row0 + r0 + u) * 128;
        *(float4*)(orow + ca)      = o0;
        *(float4*)(orow + 64 + ca) = o1;
    }
}

__global__ void __launch_bounds__(256) gemm_qkv_kernel(const float* __restrict__ q,
                                                       const float* __restrict__ hx,
                                                       const float* __restrict__ Wq,
                                                       const float* __restrict__ Wk,
                                                       const float* __restrict__ Wv)
{
    const int z = blockIdx.y;
    const float* A = (z == 0) ? q : hx;
    const float* W = (z == 0) ? Wq : (z == 1) ? Wk : Wv;
    float* Out = (z == 0) ? g_Q : (z == 1) ? g_K : g_V;
    gemm_body(A, W, Out, 0, blockIdx.x * 64);
}

__global__ void __launch_bounds__(256) gemm_out_kernel(const float* __restrict__ Wo,
                                                       float* __restrict__ Out)
{
    gemm_body(g_heads, Wo, Out, 1, blockIdx.x * 64);
}

// =====================================================================
// Fused attention v2: K/V register-resident, scores in smem.
// Block = (b, 32-row tile, head-half of 4 heads). 512 threads.
// smem floats: union(KV stage 2*256*68=34816, S 32768) + Q 2048
//              + tab 4864 + red 8192 = 49920 -> 199,680 B
// =====================================================================
__global__ void __launch_bounds__(512, 1)
attn_fused_kernel(const float* __restrict__ Ebm)
{
    extern __shared__ float sm[];
    float* U   = sm;                  // union region (KV stage, then S)
    float* Ssm = sm;                  // [4][32][256] scores
    float* Qsm = sm + 34816;          // [32][64]
    float* sT  = Qsm + 2048;          // [304][16]
    float* red = sT + 4864;           // [4][4][32][16]

    const int tid   = threadIdx.x;
    const int b     = blockIdx.y;
    const int itile = (blockIdx.x & 7) * 32;
    const int hh    = blockIdx.x >> 3;

    float* sK = U;
    float* sV = U + 256 * KVS;

    // ---- stage K/V (coalesced) + Q + table
    {
        const float* Kg = g_K + (size_t)b * NN * HK + hh * 64;
        const float* Vg = g_V + (size_t)b * NN * HK + hh * 64;
        for (int i4 = tid; i4 < 4096; i4 += 512) {
            int j = i4 >> 4, c4 = (i4 & 15) * 4;
            *(float4*)(sK + j * KVS + c4) = *(const float4*)(Kg + (size_t)j * HK + c4);
            *(float4*)(sV + j * KVS + c4) = *(const float4*)(Vg + (size_t)j * HK + c4);
        }
        int r = tid >> 4, c4 = (tid & 15) * 4;
        *(float4*)(Qsm + r * 64 + c4) =
            *(const float4*)(g_Q + (size_t)(b * NN + itile + r) * HK + hh * 64 + c4);
        for (int idx = tid; idx < 304 * 16; idx += 512) sT[idx] = g_tab[idx];
    }
    __syncthreads();

    const int warp = tid >> 5, lane = tid & 31;
    const int h   = warp & 3;        // local head
    const int jid = warp >> 2;       // j-slice 0..3
    const int jsl = jid * 64;
    const int j0 = jsl + lane, j1 = jsl + 32 + lane;

    // ---- K/V slice into registers
    float K0[16], K1[16], V0[16], V1[16];
#pragma unroll
    for (int q = 0; q < 4; q++) {
        *(float4*)(K0 + 4 * q) = *(const float4*)(sK + j0 * KVS + h * 16 + 4 * q);
        *(float4*)(K1 + 4 * q) = *(const float4*)(sK + j1 * KVS + h * 16 + 4 * q);
        *(float4*)(V0 + 4 * q) = *(const float4*)(sV + j0 * KVS + h * 16 + 4 * q);
        *(float4*)(V1 + 4 * q) = *(const float4*)(sV + j1 * KVS + h * 16 + 4 * q);
    }
    __syncthreads();   // staging reads done; U region now becomes Ssm

    // ---- P0: PWL bias (+mask) into all 4 head planes of Ssm
    {
        const int jb = tid & 63;     // lane-consecutive j for coalescing
        const int rb = tid >> 6;     // 0..7
#pragma unroll
        for (int k = 0; k < 4; k++) {
            const int r = rb + 8 * k;
            const size_t gbase = (size_t)(b * NN + itile + r) * NN;
#pragma unroll
            for (int p = 0; p < 4; p++) {
                const int j = jb + 64 * p;
                float e = Ebm[gbase + j];
                unsigned short sg = g_seg[gbase + j];
                int seg = sg & 0x7fff;
                bool mk = (sg & 0x8000) != 0;
                float4 t0 = *(const float4*)(sT + seg * 16 + hh * 8);
                float4 t1 = *(const float4*)(sT + seg * 16 + hh * 8 + 4);
                float b0 = mk ? -INFINITY : fmaf(t0.x, e, t0.y);
                float b1v = mk ? -INFINITY : fmaf(t0.z, e, t0.w);
                float b2v = mk ? -INFINITY : fmaf(t1.x, e, t1.y);
                float b3v = mk ? -INFINITY : fmaf(t1.z, e, t1.w);
                Ssm[(0 * 32 + r) * 256 + j] = b0;
                Ssm[(1 * 32 + r) * 256 + j] = b1v;
                Ssm[(2 * 32 + r) * 256 + j] = b2v;
                Ssm[(3 * 32 + r) * 256 + j] = b3v;
            }
        }
    }
    __syncthreads();

    // ---- P1: scores S += NORMC * Q.K  (K in regs, Q broadcast)
    {
        float Qr[16];
#pragma unroll 4
        for (int r = 0; r < 32; r++) {
#pragma unroll
            for (int q = 0; q < 4; q++)
                *(float4*)(Qr + 4 * q) = *(const float4*)(Qsm + r * 64 + h * 16 + 4 * q);
            float d0 = 0.f, d1 = 0.f;
#pragma unroll
            for (int k = 0; k < 16; k++) {
                d0 = fmaf(Qr[k], K0[k], d0);
                d1 = fmaf(Qr[k], K1[k], d1);
            }
            float* srow = Ssm + (h * 32 + r) * 256;
            srow[j0] = fmaf(NORMC, d0, srow[j0]);
            srow[j1] = fmaf(NORMC, d1, srow[j1]);
        }
    }
    __syncthreads();

    // ---- P2: softmax per row, in place (warp = (head, 8 rows))
    {
        const int h2 = warp & 3;
        const int rg = (warp >> 2) * 8;
#pragma unroll
        for (int rr = 0; rr < 8; rr++) {
            float* srow = Ssm + (h2 * 32 + rg + rr) * 256;
            float4 a = *(const float4*)(srow + lane * 4);
            float4 c = *(const float4*)(srow + lane * 4 + 128);
            float m = fmaxf(fmaxf(fmaxf(a.x, a.y), fmaxf(a.z, a.w)),
                            fmaxf(fmaxf(c.x, c.y), fmaxf(c.z, c.w)));
#pragma unroll
            for (int o = 16; o > 0; o >>= 1) m = fmaxf(m, __shfl_xor_sync(0xffffffffu, m, o));
            a.x = __expf(a.x - m); a.y = __expf(a.y - m);
            a.z = __expf(a.z - m); a.w = __expf(a.w - m);
            c.x = __expf(c.x - m); c.y = __expf(c.y - m);
            c.z = __expf(c.z - m); c.w = __expf(c.w - m);
            float s = a.x + a.y + a.z + a.w + c.x + c.y + c.z + c.w;
#pragma unroll
            for (int o = 16; o > 0; o >>= 1) s += __shfl_xor_sync(0xffffffffu, s, o);
            float inv = 1.f / s;
            a.x *= inv; a.y *= inv; a.z *= inv; a.w *= inv;
            c.x *= inv; c.y *= inv; c.z *= inv; c.w *= inv;
            *(float4*)(srow + lane * 4)       = a;
            *(float4*)(srow + lane * 4 + 128) = c;
        }
    }
    __syncthreads();

    // ---- P3: AV partials (V in regs), transpose-reduce, write red
    {
#pragma unroll 2
        for (int r = 0; r < 32; r++) {
            const float* srow = Ssm + (h * 32 + r) * 256;
            float p0 = srow[j0], p1 = srow[j1];
            float acc[16];
#pragma unroll
            for (int v = 0; v < 16; v++) acc[v] = fmaf(p1, V1[v], p0 * V0[v]);
#pragma unroll
            for (int i = 0; i < 16; i++) acc[i] += __shfl_xor_sync(0xffffffffu, acc[i], 16);
#pragma unroll
            for (int d = 8; d >= 1; d >>= 1) {
                int sel = lane & d;
#pragma unroll
                for (int i = 0; i < d; i++) {
                    float send = sel ? acc[i] : acc[i + d];
                    float recv = __shfl_xor_sync(0xffffffffu, send, d);
                    acc[i] = (sel ? acc[i + d] : acc[i]) + recv;
                }
            }
            if (lane < 16)
                red[((h * 4 + jid) * 32 + r) * 16 + lane] = acc[0];
        }
    }
    __syncthreads();

    // ---- P4: sum 4 j-slice partials, write g_heads
    {
#pragma unroll
        for (int k = 0; k < 4; k++) {
            int idx = tid + 512 * k;
            int v = idx & 15, r = (idx >> 4) & 31, h4 = idx >> 9;
            float s = red[((h4 * 4 + 0) * 32 + r) * 16 + v]
                    + red[((h4 * 4 + 1) * 32 + r) * 16 + v]
                    + red[((h4 * 4 + 2) * 32 + r) * 16 + v]
                    + red[((h4 * 4 + 3) * 32 + r) * 16 + v];
            g_heads[(size_t)(b * NN + itile + r) * HK + (hh * 4 + h4) * 16 + v] = s;
        }
    }
}

// =====================================================================
// host launcher
// =====================================================================
extern "C" void kernel_launch(void* const* d_in, const int* in_sizes, int n_in,
                              void* d_out, int out_size)
{
    (void)in_sizes; (void)n_in; (void)out_size;
    const float* q    = (const float*)d_in[0];
    const float* hx   = (const float*)d_in[1];
    const int*   mask = (const int*)d_in[2];
    const float* edge = (const float*)d_in[3];
    const float* Wq   = (const float*)d_in[4];
    const float* Wk   = (const float*)d_in[5];
    const float* Wv   = (const float*)d_in[6];
    const float* Wo   = (const float*)d_in[7];
    const float* mw1  = (const float*)d_in[8];
    const float* mb1  = (const float*)d_in[9];
    const float* mw2  = (const float*)d_in[10];
    const float* mb2  = (const float*)d_in[11];
    const float* mw3  = (const float*)d_in[12];
    const float* mb3  = (const float*)d_in[13];

    const int smem_gemm = (128 * 128 + 64 * AS) * 4;
    const int smem_attn = (34816 + 2048 + 4864 + 8192) * 4;   // 199,680 B

    cudaFuncSetAttribute(gemm_qkv_kernel,   cudaFuncAttributeMaxDynamicSharedMemorySize, smem_gemm);
    cudaFuncSetAttribute(gemm_out_kernel,   cudaFuncAttributeMaxDynamicSharedMemorySize, smem_gemm);
    cudaFuncSetAttribute(attn_fused_kernel, cudaFuncAttributeMaxDynamicSharedMemorySize, smem_attn);

    pwl_build_kernel<<<1, 512>>>(mw1, mb1, mw2, mb2, mw3, mb3);

    gemm_qkv_kernel<<<dim3(ROWS / 64, 3), 256, smem_gemm>>>(q, hx, Wq, Wk, Wv);

    seg_kernel<<<(BB * NN * NN) / (512 * 4), 512>>>(edge, mask);

    attn_fused_kernel<<<dim3(16, BB), 512, smem_attn>>>(edge);

    gemm_out_kernel<<<ROWS / 64, 256, smem_gemm>>>(Wo, (float*)d_out);
}

// round 7
// speedup vs baseline: 1.2079x; 1.2079x over previous
#include <cuda_runtime.h>
#include <math.h>
#include <stdint.h>

// Problem constants
#define BB   128
#define NN   256
#define DIN  128
#define HH   8
#define DK   16
#define HK   128
#define ROWS (BB*NN)        // 32768
#define NORMC 0.25f
#define AS   132            // GEMM A smem stride
#define SST  260            // score smem row stride (mult of 4)
#define KST  20             // K smem row stride

// ---------------- device-global scratch ----------------
// Q/K/V in head-major layout: [h][b*N+n][16]
__device__ float g_Q[(size_t)HH * ROWS * DK];
__device__ float g_K[(size_t)HH * ROWS * DK];
__device__ float g_V[(size_t)HH * ROWS * DK];
__device__ float g_heads[(size_t)ROWS * HK];   // [b*N+q][h*16+v]

__device__ float g_breaks[512];
__device__ float g_tab[512 * 16];              // [seg][h*2]=slope,[h*2+1]=inter
__device__ unsigned short g_seg[(size_t)BB * NN * NN];

// =====================================================================
// PWL build (one block, 512 threads)
// =====================================================================
__global__ void pwl_build_kernel(const float* __restrict__ mw1, const float* __restrict__ mb1,
                                 const float* __restrict__ mw2, const float* __restrict__ mb2,
                                 const float* __restrict__ mw3, const float* __restrict__ mb3)
{
    __shared__ float w1[16], b1[16], w2[256], b2[16], w3[128], b3[8];
    __shared__ float tsort[16];
    __shared__ float cand[512];
    __shared__ int   cnt;

    const int tid = threadIdx.x;
    if (tid < 16)  { w1[tid] = mw1[tid]; b1[tid] = mb1[tid]; b2[tid] = mb2[tid]; }
    if (tid < 256) w2[tid] = mw2[tid];
    if (tid < 128) w3[tid] = mw3[tid];
    if (tid < 8)   b3[tid] = mb3[tid];
    cand[tid] = 3.0e38f;
    if (tid == 0) cnt = 16;
    __syncthreads();

    if (tid < 16) {
        float t = (w1[tid] != 0.f) ? (-b1[tid] / w1[tid]) : 3.0e38f;
        cand[tid] = t;
    }
    __syncthreads();
    if (tid == 0) {
        for (int i = 0; i < 16; i++) tsort[i] = cand[i];
        for (int i = 1; i < 16; i++) {
            float v = tsort[i]; int k = i - 1;
            while (k >= 0 && tsort[k] > v) { tsort[k + 1] = tsort[k]; k--; }
            tsort[k + 1] = v;
        }
    }
    __syncthreads();

    if (tid < 17 * 16) {
        int iv = tid >> 4, c = tid & 15;
        float lo = (iv == 0)  ? -3.0e38f : tsort[iv - 1];
        float hi = (iv == 16) ?  3.0e38f : tsort[iv];
        if (lo < hi) {
            float m;
            if (lo <= -1e30f && hi >= 1e30f) m = 0.f;
            else if (lo <= -1e30f)           m = hi - 1.f;
            else if (hi >=  1e30f)           m = lo + 1.f;
            else                             m = 0.5f * (lo + hi);
            float g = 0.f, q = b2[c];
            for (int n = 0; n < 16; n++) {
                if (fmaf(m, w1[n], b1[n]) > 0.f) {
                    g = fmaf(w1[n], w2[n * 16 + c], g);
                    q = fmaf(b1[n], w2[n * 16 + c], q);
                }
            }
            if (g != 0.f) {
                float x = -q / g;
                if (x > lo && x < hi && fabsf(x) < 1e30f) {
                    int k = atomicAdd(&cnt, 1);
                    cand[k] = x;
                }
            }
        }
    }
    __syncthreads();
    const int ncand = cnt;

    for (int k = 2; k <= 512; k <<= 1) {
        for (int j = k >> 1; j > 0; j >>= 1) {
            int ixj = tid ^ j;
            if (ixj > tid) {
                bool up = (tid & k) == 0;
                float a = cand[tid], b = cand[ixj];
                if ((a > b) == up) { cand[tid] = b; cand[ixj] = a; }
            }
            __syncthreads();
        }
    }

    g_breaks[tid] = (tid < ncand) ? cand[tid] : 3.0e38f;

    if (tid <= ncand) {
        float lo = (tid == 0)     ? -3.0e38f : cand[tid - 1];
        float hi = (tid == ncand) ?  3.0e38f : cand[tid];
        float m;
        if (lo <= -1e30f && hi >= 1e30f) m = 0.f;
        else if (lo <= -1e30f)           m = hi - 1.f;
        else if (hi >=  1e30f)           m = lo + 1.f;
        else                             m = 0.5f * (lo + hi);

        float slope[8], inter[8];
        for (int h = 0; h < 8; h++) { slope[h] = 0.f; inter[h] = b3[h]; }
        for (int c = 0; c < 16; c++) {
            float gc = 0.f, qc = b2[c];
            for (int n = 0; n < 16; n++) {
                if (fmaf(m, w1[n], b1[n]) > 0.f) {
                    gc = fmaf(w1[n], w2[n * 16 + c], gc);
                    qc = fmaf(b1[n], w2[n * 16 + c], qc);
                }
            }
            if (fmaf(gc, m, qc) > 0.f) {
                for (int h = 0; h < 8; h++) {
                    slope[h] = fmaf(gc, w3[c * 8 + h], slope[h]);
                    inter[h] = fmaf(qc, w3[c * 8 + h], inter[h]);
                }
            }
        }
        for (int h = 0; h < 8; h++) {
            g_tab[tid * 16 + h * 2]     = slope[h];
            g_tab[tid * 16 + h * 2 + 1] = inter[h];
        }
    }
}

// =====================================================================
// seg kernel
// =====================================================================
__global__ void __launch_bounds__(512) seg_kernel(const float* __restrict__ Ebm,
                                                  const int* __restrict__ mask)
{
    __shared__ float sB[512];
    const int tid = threadIdx.x;
    sB[tid] = g_breaks[tid];
    __syncthreads();

    const size_t v = (size_t)blockIdx.x * 512 + tid;
    float4 e4 = ((const float4*)Ebm)[v];
    int4   m4 = ((const int4*)mask)[v];
    ushort4 out;
    const float ev[4] = {e4.x, e4.y, e4.z, e4.w};
    const int   mv[4] = {m4.x, m4.y, m4.z, m4.w};
    unsigned short ov[4];
#pragma unroll
    for (int p = 0; p < 4; p++) {
        float e = ev[p];
        int seg = 0;
#pragma unroll
        for (int st = 256; st >= 1; st >>= 1) {
            int cnd = seg + st;
            if (e >= sB[cnd - 1]) seg = cnd;
        }
        ov[p] = (unsigned short)(seg | (mv[p] ? 0x8000 : 0));
    }
    out.x = ov[0]; out.y = ov[1]; out.z = ov[2]; out.w = ov[3];
    ((ushort4*)g_seg)[v] = out;
}

// =====================================================================
// GEMM body. mode 0: QKV -> head-major output [h][row][16]
//            mode 1: row-major 128-wide output
// =====================================================================
__device__ __forceinline__ void gemm_body(const float* __restrict__ A,
                                          const float* __restrict__ Wraw,
                                          float* __restrict__ Out,
                                          int mode, int row0)
{
    extern __shared__ float sm[];
    float* Wsm = sm;
    float* Asm = sm + 128 * 128;

    const int tid = threadIdx.x;

    for (int i4 = tid; i4 < 4096; i4 += 256) {
        int d = i4 >> 5, c4 = (i4 & 31) * 4;
        float4 w;
        if (mode == 0) w = *(const float4*)(Wraw + (c4 >> 4) * (DIN * 16) + d * 16 + (c4 & 15));
        else           w = *(const float4*)(Wraw + d * 128 + c4);
        *(float4*)(Wsm + d * 128 + c4) = w;
    }
    for (int i4 = tid; i4 < 2048; i4 += 256) {
        int r = i4 >> 5, c4 = (i4 & 31) * 4;
        *(float4*)(Asm + r * AS + c4) = *(const float4*)(A + (size_t)(row0 + r) * 128 + c4);
    }
    __syncthreads();

    const int tx = tid & 15, ty = tid >> 4;
    const int ca = tx * 4;
    const int r0 = ty * 4;
    float acc[4][8];
#pragma unroll
    for (int u = 0; u < 4; u++)
#pragma unroll
        for (int k = 0; k < 8; k++) acc[u][k] = 0.f;

#pragma unroll 2
    for (int dc = 0; dc < 128; dc += 4) {
        float4 a4[4];
#pragma unroll
        for (int u = 0; u < 4; u++) a4[u] = *(const float4*)(Asm + (r0 + u) * AS + dc);
#pragma unroll
        for (int dd = 0; dd < 4; dd++) {
            float4 w0 = *(const float4*)(Wsm + (dc + dd) * 128 + ca);
            float4 w1 = *(const float4*)(Wsm + (dc + dd) * 128 + 64 + ca);
            float wv[8] = {w0.x, w0.y, w0.z, w0.w, w1.x, w1.y, w1.z, w1.w};
#pragma unroll
            for (int u = 0; u < 4; u++) {
                float a = (dd == 0) ? a4[u].x : (dd == 1) ? a4[u].y : (dd == 2) ? a4[u].z : a4[u].w;
#pragma unroll
                for (int k = 0; k < 8; k++) acc[u][k] = fmaf(a, wv[k], acc[u][k]);
            }
        }
    }
#pragma unroll
    for (int u = 0; u < 4; u++) {
        float4 o0 = {acc[u][0], acc[u][1], acc[u][2], acc[u][3]};
        float4 o1 = {acc[u][4], acc[u][5], acc[u][6], acc[u][7]};
        const int row = row0 + r0 + u;
        if (mode == 0) {
            int h0 = ca >> 4, h1 = (64 + ca) >> 4;
            *(float4*)(Out + ((size_t)h0 * ROWS + row) * 16 + (ca & 15)) = o0;
            *(float4*)(Out + ((size_t)h1 * ROWS + row) * 16 + (ca & 15)) = o1;
        } else {
            float* orow = Out + (size_t)row * 128;
            *(float4*)(orow + ca)      = o0;
            *(float4*)(orow + 64 + ca) = o1;
        }
    }
}

__global__ void __launch_bounds__(256) gemm_qkv_kernel(const float* __restrict__ q,
                                                       const float* __restrict__ hx,
                                                       const float* __restrict__ Wq,
                                                       const float* __restrict__ Wk,
                                                       const float* __restrict__ Wv)
{
    const int z = blockIdx.y;
    const float* A = (z == 0) ? q : hx;
    const float* W = (z == 0) ? Wq : (z == 1) ? Wk : Wv;
    float* Out = (z == 0) ? g_Q : (z == 1) ? g_K : g_V;
    gemm_body(A, W, Out, 0, blockIdx.x * 64);
}

__global__ void __launch_bounds__(256) gemm_out_kernel(const float* __restrict__ Wo,
                                                       float* __restrict__ Out)
{
    gemm_body(g_heads, Wo, Out, 1, blockIdx.x * 64);
}

// =====================================================================
// Fused attention v3: one head per block, 2 blocks/SM, no shuffles.
// Block = (b, 32-row i-tile, head). 512 threads.
// smem (floats): S 32*260=8320 | K 256*20=5120 | V 256*16=4096 |
//                Q 32*16=512 | tab 304*2=608 | red 16*32*20=10240
//                total 28896 f = 115,584 B
// =====================================================================
__global__ void __launch_bounds__(512, 2)
attn_fused_kernel(const float* __restrict__ Ebm)
{
    extern __shared__ float sm[];
    float* Ssm = sm;                 // [32][260]
    float* sK  = Ssm + 32 * SST;     // [256][20]
    float* sV  = sK + 256 * KST;     // [256][16]
    float* Qsm = sV + 256 * 16;      // [32][16]  (pre-scaled by NORMC)
    float* sT  = Qsm + 512;          // [304][2]
    float* red = sT + 608;           // [16][32][20]

    const int tid   = threadIdx.x;
    const int b     = blockIdx.y;
    const int itile = (blockIdx.x & 7) * 32;
    const int head  = blockIdx.x >> 3;

    const size_t hbase = (size_t)head * ROWS + (size_t)b * NN;   // row base in head-major

    // ---- stage K, V, Q, table (all contiguous global reads)
    {
        const float4* Kg = (const float4*)(g_K + hbase * 16);
        const float4* Vg = (const float4*)(g_V + hbase * 16);
#pragma unroll
        for (int p = 0; p < 2; p++) {
            int q4 = tid + 512 * p;            // 0..1023 quads
            int j = q4 >> 2, cq = (q4 & 3) * 4;
            *(float4*)(sK + j * KST + cq) = Kg[q4];
            *(float4*)(sV + j * 16  + cq) = Vg[q4];
        }
        if (tid < 128) {
            float4 qv = *(const float4*)(g_Q + (hbase + itile) * 16 + tid * 4);
            qv.x *= NORMC; qv.y *= NORMC; qv.z *= NORMC; qv.w *= NORMC;
            *(float4*)(Qsm + tid * 4) = qv;
        }
        if (tid < 304) {
            sT[tid * 2]     = g_tab[tid * 16 + head * 2];
            sT[tid * 2 + 1] = g_tab[tid * 16 + head * 2 + 1];
        }
    }
    __syncthreads();

    const int warp = tid >> 5, lane = tid & 31;

    // ---- K slice into registers: warp = (jq8 = warp&7, rh = warp>>3)
    const int jq8 = warp & 7;
    const int rh  = warp >> 3;
    const int jgl = jq8 * 32 + lane;
    float K0[16];
#pragma unroll
    for (int qq = 0; qq < 4; qq++)
        *(float4*)(K0 + 4 * qq) = *(const float4*)(sK + jgl * KST + 4 * qq);

    // ---- P0: PWL bias (+mask) into S (this head's plane only)
    {
#pragma unroll
        for (int p = 0; p < 4; p++) {
            int q4 = tid + 512 * p;            // 2048 float4-cells
            int r = q4 >> 6, j4 = (q4 & 63) * 4;
            const size_t gi = (size_t)(b * NN + itile + r) * NN + j4;
            float4 e4 = *(const float4*)(Ebm + gi);
            ushort4 s4 = *(const ushort4*)(g_seg + gi);
            const float ev[4] = {e4.x, e4.y, e4.z, e4.w};
            const unsigned short sv[4] = {s4.x, s4.y, s4.z, s4.w};
            float bv[4];
#pragma unroll
            for (int u = 0; u < 4; u++) {
                int seg = sv[u] & 0x7fff;
                float2 t = *(const float2*)(sT + seg * 2);
                bv[u] = (sv[u] & 0x8000) ? -INFINITY : fmaf(t.x, ev[u], t.y);
            }
            *(float4*)(Ssm + r * SST + j4) = make_float4(bv[0], bv[1], bv[2], bv[3]);
        }
    }
    __syncthreads();

    // ---- P1: S += Q.K  (Q pre-scaled; K in regs; rows rh*16..rh*16+15)
    {
        const int rbase = rh * 16;
#pragma unroll 4
        for (int rr = 0; rr < 16; rr++) {
            const int r = rbase + rr;
            const float* qp = Qsm + r * 16;
            float4 q0 = *(const float4*)(qp);
            float4 q1 = *(const float4*)(qp + 4);
            float4 q2 = *(const float4*)(qp + 8);
            float4 q3 = *(const float4*)(qp + 12);
            float d = 0.f;
            d = fmaf(q0.x, K0[0], d);  d = fmaf(q0.y, K0[1], d);
            d = fmaf(q0.z, K0[2], d);  d = fmaf(q0.w, K0[3], d);
            d = fmaf(q1.x, K0[4], d);  d = fmaf(q1.y, K0[5], d);
            d = fmaf(q1.z, K0[6], d);  d = fmaf(q1.w, K0[7], d);
            d = fmaf(q2.x, K0[8], d);  d = fmaf(q2.y, K0[9], d);
            d = fmaf(q2.z, K0[10], d); d = fmaf(q2.w, K0[11], d);
            d = fmaf(q3.x, K0[12], d); d = fmaf(q3.y, K0[13], d);
            d = fmaf(q3.z, K0[14], d); d = fmaf(q3.w, K0[15], d);
            Ssm[r * SST + jgl] += d;
        }
    }
    __syncthreads();

    // ---- P2: softmax per row, in place (warp = 2 rows)
    {
#pragma unroll
        for (int rr = 0; rr < 2; rr++) {
            float* srow = Ssm + (warp * 2 + rr) * SST;
            float4 a = *(const float4*)(srow + lane * 4);
            float4 c = *(const float4*)(srow + lane * 4 + 128);
            float m = fmaxf(fmaxf(fmaxf(a.x, a.y), fmaxf(a.z, a.w)),
                            fmaxf(fmaxf(c.x, c.y), fmaxf(c.z, c.w)));
#pragma unroll
            for (int o = 16; o > 0; o >>= 1) m = fmaxf(m, __shfl_xor_sync(0xffffffffu, m, o));
            a.x = __expf(a.x - m); a.y = __expf(a.y - m);
            a.z = __expf(a.z - m); a.w = __expf(a.w - m);
            c.x = __expf(c.x - m); c.y = __expf(c.y - m);
            c.z = __expf(c.z - m); c.w = __expf(c.w - m);
            float s = a.x + a.y + a.z + a.w + c.x + c.y + c.z + c.w;
#pragma unroll
            for (int o = 16; o > 0; o >>= 1) s += __shfl_xor_sync(0xffffffffu, s, o);
            float inv = 1.f / s;
            a.x *= inv; a.y *= inv; a.z *= inv; a.w *= inv;
            c.x *= inv; c.y *= inv; c.z *= inv; c.w *= inv;
            *(float4*)(srow + lane * 4)       = a;
            *(float4*)(srow + lane * 4 + 128) = c;
        }
    }
    __syncthreads();

    // ---- P3: AV, transpose-free. warp = 16-j group; lane = row.
    {
        const int j0 = warp * 16;
        float acc[16];
#pragma unroll
        for (int v = 0; v < 16; v++) acc[v] = 0.f;
#pragma unroll
        for (int jj = 0; jj < 16; jj++) {
            const int j = j0 + jj;
            float p = Ssm[lane * SST + j];          // 4-way bank conflict (stride 260)
            const float4* vp = (const float4*)(sV + j * 16);   // broadcast
            float4 v0 = vp[0], v1 = vp[1], v2 = vp[2], v3 = vp[3];
            acc[0]  = fmaf(p, v0.x, acc[0]);  acc[1]  = fmaf(p, v0.y, acc[1]);
            acc[2]  = fmaf(p, v0.z, acc[2]);  acc[3]  = fmaf(p, v0.w, acc[3]);
            acc[4]  = fmaf(p, v1.x, acc[4]);  acc[5]  = fmaf(p, v1.y, acc[5]);
            acc[6]  = fmaf(p, v1.z, acc[6]);  acc[7]  = fmaf(p, v1.w, acc[7]);
            acc[8]  = fmaf(p, v2.x, acc[8]);  acc[9]  = fmaf(p, v2.y, acc[9]);
            acc[10] = fmaf(p, v2.z, acc[10]); acc[11] = fmaf(p, v2.w, acc[11]);
            acc[12] = fmaf(p, v3.x, acc[12]); acc[13] = fmaf(p, v3.y, acc[13]);
            acc[14] = fmaf(p, v3.z, acc[14]); acc[15] = fmaf(p, v3.w, acc[15]);
        }
        float* rp = red + (warp * 32 + lane) * 20;
#pragma unroll
        for (int qq = 0; qq < 4; qq++)
            *(float4*)(rp + qq * 4) = make_float4(acc[qq*4], acc[qq*4+1], acc[qq*4+2], acc[qq*4+3]);
    }
    __syncthreads();

    // ---- P4: sum 16 j-group partials, write g_heads
    {
        const int r = tid >> 4, v = tid & 15;
        float s = 0.f;
#pragma unroll
        for (int jq = 0; jq < 16; jq++)
            s += red[(jq * 32 + r) * 20 + v];
        g_heads[(size_t)(b * NN + itile + r) * HK + head * 16 + v] = s;
    }
}

// =====================================================================
// host launcher
// =====================================================================
extern "C" void kernel_launch(void* const* d_in, const int* in_sizes, int n_in,
                              void* d_out, int out_size)
{
    (void)in_sizes; (void)n_in; (void)out_size;
    const float* q    = (const float*)d_in[0];
    const float* hx   = (const float*)d_in[1];
    const int*   mask = (const int*)d_in[2];
    const float* edge = (const float*)d_in[3];
    const float* Wq   = (const float*)d_in[4];
    const float* Wk   = (const float*)d_in[5];
    const float* Wv   = (const float*)d_in[6];
    const float* Wo   = (const float*)d_in[7];
    const float* mw1  = (const float*)d_in[8];
    const float* mb1  = (const float*)d_in[9];
    const float* mw2  = (const float*)d_in[10];
    const float* mb2  = (const float*)d_in[11];
    const float* mw3  = (const float*)d_in[12];
    const float* mb3  = (const float*)d_in[13];

    const int smem_gemm = (128 * 128 + 64 * AS) * 4;
    const int smem_attn = (32 * SST + 256 * KST + 256 * 16 + 512 + 608 + 16 * 32 * 20) * 4;

    cudaFuncSetAttribute(gemm_qkv_kernel,   cudaFuncAttributeMaxDynamicSharedMemorySize, smem_gemm);
    cudaFuncSetAttribute(gemm_out_kernel,   cudaFuncAttributeMaxDynamicSharedMemorySize, smem_gemm);
    cudaFuncSetAttribute(attn_fused_kernel, cudaFuncAttributeMaxDynamicSharedMemorySize, smem_attn);

    pwl_build_kernel<<<1, 512>>>(mw1, mb1, mw2, mb2, mw3, mb3);

    gemm_qkv_kernel<<<dim3(ROWS / 64, 3), 256, smem_gemm>>>(q, hx, Wq, Wk, Wv);

    seg_kernel<<<(BB * NN * NN) / (512 * 4), 512>>>(edge, mask);

    attn_fused_kernel<<<dim3(64, BB), 512, smem_attn>>>(edge);

    gemm_out_kernel<<<ROWS / 64, 256, smem_gemm>>>(Wo, (float*)d_out);
}

// round 8
// speedup vs baseline: 1.2158x; 1.0065x over previous
#include <cuda_runtime.h>
#include <math.h>
#include <stdint.h>

// Problem constants
#define BB   128
#define NN   256
#define DIN  128
#define HH   8
#define DK   16
#define HK   128
#define ROWS (BB*NN)        // 32768
#define NORMC 0.25f
#define AS   132            // GEMM A smem stride
#define SST  260            // score row stride (f4-friendly)
#define PTS  257            // prob row stride (odd => conflict-free columns)
#define RST  17             // red row stride (odd)

// ---------------- device-global scratch ----------------
// Q/K/V head-major: [h][b*N+n][16]
__device__ float g_Q[(size_t)HH * ROWS * DK];
__device__ float g_K[(size_t)HH * ROWS * DK];
__device__ float g_V[(size_t)HH * ROWS * DK];
__device__ float g_heads[(size_t)ROWS * HK];

__device__ float g_breaks[512];
__device__ float g_tab[512 * 16];
__device__ unsigned short g_seg[(size_t)BB * NN * NN];

// =====================================================================
// PWL build (one block, 512 threads)
// =====================================================================
__global__ void pwl_build_kernel(const float* __restrict__ mw1, const float* __restrict__ mb1,
                                 const float* __restrict__ mw2, const float* __restrict__ mb2,
                                 const float* __restrict__ mw3, const float* __restrict__ mb3)
{
    __shared__ float w1[16], b1[16], w2[256], b2[16], w3[128], b3[8];
    __shared__ float tsort[16];
    __shared__ float cand[512];
    __shared__ int   cnt;

    const int tid = threadIdx.x;
    if (tid < 16)  { w1[tid] = mw1[tid]; b1[tid] = mb1[tid]; b2[tid] = mb2[tid]; }
    if (tid < 256) w2[tid] = mw2[tid];
    if (tid < 128) w3[tid] = mw3[tid];
    if (tid < 8)   b3[tid] = mb3[tid];
    cand[tid] = 3.0e38f;
    if (tid == 0) cnt = 16;
    __syncthreads();

    if (tid < 16) {
        float t = (w1[tid] != 0.f) ? (-b1[tid] / w1[tid]) : 3.0e38f;
        cand[tid] = t;
    }
    __syncthreads();
    if (tid == 0) {
        for (int i = 0; i < 16; i++) tsort[i] = cand[i];
        for (int i = 1; i < 16; i++) {
            float v = tsort[i]; int k = i - 1;
            while (k >= 0 && tsort[k] > v) { tsort[k + 1] = tsort[k]; k--; }
            tsort[k + 1] = v;
        }
    }
    __syncthreads();

    if (tid < 17 * 16) {
        int iv = tid >> 4, c = tid & 15;
        float lo = (iv == 0)  ? -3.0e38f : tsort[iv - 1];
        float hi = (iv == 16) ?  3.0e38f : tsort[iv];
        if (lo < hi) {
            float m;
            if (lo <= -1e30f && hi >= 1e30f) m = 0.f;
            else if (lo <= -1e30f)           m = hi - 1.f;
            else if (hi >=  1e30f)           m = lo + 1.f;
            else                             m = 0.5f * (lo + hi);
            float g = 0.f, q = b2[c];
            for (int n = 0; n < 16; n++) {
                if (fmaf(m, w1[n], b1[n]) > 0.f) {
                    g = fmaf(w1[n], w2[n * 16 + c], g);
                    q = fmaf(b1[n], w2[n * 16 + c], q);
                }
            }
            if (g != 0.f) {
                float x = -q / g;
                if (x > lo && x < hi && fabsf(x) < 1e30f) {
                    int k = atomicAdd(&cnt, 1);
                    cand[k] = x;
                }
            }
        }
    }
    __syncthreads();
    const int ncand = cnt;

    for (int k = 2; k <= 512; k <<= 1) {
        for (int j = k >> 1; j > 0; j >>= 1) {
            int ixj = tid ^ j;
            if (ixj > tid) {
                bool up = (tid & k) == 0;
                float a = cand[tid], b = cand[ixj];
                if ((a > b) == up) { cand[tid] = b; cand[ixj] = a; }
            }
            __syncthreads();
        }
    }

    g_breaks[tid] = (tid < ncand) ? cand[tid] : 3.0e38f;

    if (tid <= ncand) {
        float lo = (tid == 0)     ? -3.0e38f : cand[tid - 1];
        float hi = (tid == ncand) ?  3.0e38f : cand[tid];
        float m;
        if (lo <= -1e30f && hi >= 1e30f) m = 0.f;
        else if (lo <= -1e30f)           m = hi - 1.f;
        else if (hi >=  1e30f)           m = lo + 1.f;
        else                             m = 0.5f * (lo + hi);

        float slope[8], inter[8];
        for (int h = 0; h < 8; h++) { slope[h] = 0.f; inter[h] = b3[h]; }
        for (int c = 0; c < 16; c++) {
            float gc = 0.f, qc = b2[c];
            for (int n = 0; n < 16; n++) {
                if (fmaf(m, w1[n], b1[n]) > 0.f) {
                    gc = fmaf(w1[n], w2[n * 16 + c], gc);
                    qc = fmaf(b1[n], w2[n * 16 + c], qc);
                }
            }
            if (fmaf(gc, m, qc) > 0.f) {
                for (int h = 0; h < 8; h++) {
                    slope[h] = fmaf(gc, w3[c * 8 + h], slope[h]);
                    inter[h] = fmaf(qc, w3[c * 8 + h], inter[h]);
                }
            }
        }
        for (int h = 0; h < 8; h++) {
            g_tab[tid * 16 + h * 2]     = slope[h];
            g_tab[tid * 16 + h * 2 + 1] = inter[h];
        }
    }
}

// =====================================================================
// seg kernel
// =====================================================================
__global__ void __launch_bounds__(512) seg_kernel(const float* __restrict__ Ebm,
                                                  const int* __restrict__ mask)
{
    __shared__ float sB[512];
    const int tid = threadIdx.x;
    sB[tid] = g_breaks[tid];
    __syncthreads();

    const size_t v = (size_t)blockIdx.x * 512 + tid;
    float4 e4 = ((const float4*)Ebm)[v];
    int4   m4 = ((const int4*)mask)[v];
    ushort4 out;
    const float ev[4] = {e4.x, e4.y, e4.z, e4.w};
    const int   mv[4] = {m4.x, m4.y, m4.z, m4.w};
    unsigned short ov[4];
#pragma unroll
    for (int p = 0; p < 4; p++) {
        float e = ev[p];
        int seg = 0;
#pragma unroll
        for (int st = 256; st >= 1; st >>= 1) {
            int cnd = seg + st;
            if (e >= sB[cnd - 1]) seg = cnd;
        }
        ov[p] = (unsigned short)(seg | (mv[p] ? 0x8000 : 0));
    }
    out.x = ov[0]; out.y = ov[1]; out.z = ov[2]; out.w = ov[3];
    ((ushort4*)g_seg)[v] = out;
}

// =====================================================================
// GEMM body (as R7)
// =====================================================================
__device__ __forceinline__ void gemm_body(const float* __restrict__ A,
                                          const float* __restrict__ Wraw,
                                          float* __restrict__ Out,
                                          int mode, int row0)
{
    extern __shared__ float sm[];
    float* Wsm = sm;
    float* Asm = sm + 128 * 128;

    const int tid = threadIdx.x;

    for (int i4 = tid; i4 < 4096; i4 += 256) {
        int d = i4 >> 5, c4 = (i4 & 31) * 4;
        float4 w;
        if (mode == 0) w = *(const float4*)(Wraw + (c4 >> 4) * (DIN * 16) + d * 16 + (c4 & 15));
        else           w = *(const float4*)(Wraw + d * 128 + c4);
        *(float4*)(Wsm + d * 128 + c4) = w;
    }
    for (int i4 = tid; i4 < 2048; i4 += 256) {
        int r = i4 >> 5, c4 = (i4 & 31) * 4;
        *(float4*)(Asm + r * AS + c4) = *(const float4*)(A + (size_t)(row0 + r) * 128 + c4);
    }
    __syncthreads();

    const int tx = tid & 15, ty = tid >> 4;
    const int ca = tx * 4;
    const int r0 = ty * 4;
    float acc[4][8];
#pragma unroll
    for (int u = 0; u < 4; u++)
#pragma unroll
        for (int k = 0; k < 8; k++) acc[u][k] = 0.f;

#pragma unroll 2
    for (int dc = 0; dc < 128; dc += 4) {
        float4 a4[4];
#pragma unroll
        for (int u = 0; u < 4; u++) a4[u] = *(const float4*)(Asm + (r0 + u) * AS + dc);
#pragma unroll
        for (int dd = 0; dd < 4; dd++) {
            float4 w0 = *(const float4*)(Wsm + (dc + dd) * 128 + ca);
            float4 w1 = *(const float4*)(Wsm + (dc + dd) * 128 + 64 + ca);
            float wv[8] = {w0.x, w0.y, w0.z, w0.w, w1.x, w1.y, w1.z, w1.w};
#pragma unroll
            for (int u = 0; u < 4; u++) {
                float a = (dd == 0) ? a4[u].x : (dd == 1) ? a4[u].y : (dd == 2) ? a4[u].z : a4[u].w;
#pragma unroll
                for (int k = 0; k < 8; k++) acc[u][k] = fmaf(a, wv[k], acc[u][k]);
            }
        }
    }
#pragma unroll
    for (int u = 0; u < 4; u++) {
        float4 o0 = {acc[u][0], acc[u][1], acc[u][2], acc[u][3]};
        float4 o1 = {acc[u][4], acc[u][5], acc[u][6], acc[u][7]};
        const int row = row0 + r0 + u;
        if (mode == 0) {
            int h0 = ca >> 4, h1 = (64 + ca) >> 4;
            *(float4*)(Out + ((size_t)h0 * ROWS + row) * 16 + (ca & 15)) = o0;
            *(float4*)(Out + ((size_t)h1 * ROWS + row) * 16 + (ca & 15)) = o1;
        } else {
            float* orow = Out + (size_t)row * 128;
            *(float4*)(orow + ca)      = o0;
            *(float4*)(orow + 64 + ca) = o1;
        }
    }
}

__global__ void __launch_bounds__(256) gemm_qkv_kernel(const float* __restrict__ q,
                                                       const float* __restrict__ hx,
                                                       const float* __restrict__ Wq,
                                                       const float* __restrict__ Wk,
                                                       const float* __restrict__ Wv)
{
    const int z = blockIdx.y;
    const float* A = (z == 0) ? q : hx;
    const float* W = (z == 0) ? Wq : (z == 1) ? Wk : Wv;
    float* Out = (z == 0) ? g_Q : (z == 1) ? g_K : g_V;
    gemm_body(A, W, Out, 0, blockIdx.x * 64);
}

__global__ void __launch_bounds__(256) gemm_out_kernel(const float* __restrict__ Wo,
                                                       float* __restrict__ Out)
{
    gemm_body(g_heads, Wo, Out, 1, blockIdx.x * 64);
}

// =====================================================================
// Fused attention v4: conflict-free smem schedule.
// Block = (b, 32-row tile, head). 512 threads, 2 blocks/SM.
// smem (floats): A = union(S 32x260=8320, red 16x32x17=8704) -> 8704
//                Pt 32x257=8224 | V 4096 | Q 512 | tab 608
//                total 22144 f = 88,576 B
// =====================================================================
__global__ void __launch_bounds__(512, 2)
attn_fused_kernel(const float* __restrict__ Ebm)
{
    extern __shared__ float sm[];
    float* Ssm = sm;                 // [32][260]
    float* red = sm;                 // [16][32][17]  (overlays S after P2)
    float* Pt  = sm + 8704;          // [32][257]
    float* sV  = Pt + 8224;          // [256][16]
    float* Qsm = sV + 4096;          // [32][16] (pre-scaled by NORMC)
    float* sT  = Qsm + 512;          // [304][2]

    const int tid   = threadIdx.x;
    const int b     = blockIdx.y;
    const int itile = (blockIdx.x & 7) * 32;
    const int head  = blockIdx.x >> 3;

    const size_t hbase = (size_t)head * ROWS + (size_t)b * NN;

    const int warp = tid >> 5, lane = tid & 31;
    const int jq8 = warp & 7;
    const int jgl = jq8 * 32 + lane;
    const int rh  = warp >> 3;

    // ---- K straight from global into registers (no smem staging)
    float K0[16];
    {
        const float4* Kg = (const float4*)(g_K + (hbase + jgl) * 16);
#pragma unroll
        for (int qq = 0; qq < 4; qq++) *(float4*)(K0 + 4 * qq) = Kg[qq];
    }

    // ---- stage V (contiguous copy), Q (scaled), table
    {
        const float4* Vg = (const float4*)(g_V + hbase * 16);
#pragma unroll
        for (int p = 0; p < 2; p++) {
            int q4 = tid + 512 * p;               // 1024 quads
            *(float4*)(sV + q4 * 4) = Vg[q4];
        }
        if (tid < 128) {
            float4 qv = *(const float4*)(g_Q + (hbase + itile) * 16 + tid * 4);
            qv.x *= NORMC; qv.y *= NORMC; qv.z *= NORMC; qv.w *= NORMC;
            *(float4*)(Qsm + tid * 4) = qv;
        }
        if (tid < 304) {
            sT[tid * 2]     = g_tab[tid * 16 + head * 2];
            sT[tid * 2 + 1] = g_tab[tid * 16 + head * 2 + 1];
        }
    }
    __syncthreads();

    // ---- P0: PWL bias (+mask) into S (f4 rows, stride 260)
    {
#pragma unroll
        for (int p = 0; p < 4; p++) {
            int q4 = tid + 512 * p;
            int r = q4 >> 6, j4 = (q4 & 63) * 4;
            const size_t gi = (size_t)(b * NN + itile + r) * NN + j4;
            float4 e4 = *(const float4*)(Ebm + gi);
            ushort4 s4 = *(const ushort4*)(g_seg + gi);
            const float ev[4] = {e4.x, e4.y, e4.z, e4.w};
            const unsigned short sv[4] = {s4.x, s4.y, s4.z, s4.w};
            float bv[4];
#pragma unroll
            for (int u = 0; u < 4; u++) {
                int seg = sv[u] & 0x7fff;
                float2 t = *(const float2*)(sT + seg * 2);
                bv[u] = (sv[u] & 0x8000) ? -INFINITY : fmaf(t.x, ev[u], t.y);
            }
            *(float4*)(Ssm + r * SST + j4) = make_float4(bv[0], bv[1], bv[2], bv[3]);
        }
    }
    __syncthreads();

    // ---- P1: S += Q.K  (Q pre-scaled broadcast; K regs; rows rh*16..+15)
    {
        const int rbase = rh * 16;
#pragma unroll 4
        for (int rr = 0; rr < 16; rr++) {
            const int r = rbase + rr;
            const float* qp = Qsm + r * 16;
            float4 q0 = *(const float4*)(qp);
            float4 q1 = *(const float4*)(qp + 4);
            float4 q2 = *(const float4*)(qp + 8);
            float4 q3 = *(const float4*)(qp + 12);
            float d = 0.f;
            d = fmaf(q0.x, K0[0], d);  d = fmaf(q0.y, K0[1], d);
            d = fmaf(q0.z, K0[2], d);  d = fmaf(q0.w, K0[3], d);
            d = fmaf(q1.x, K0[4], d);  d = fmaf(q1.y, K0[5], d);
            d = fmaf(q1.z, K0[6], d);  d = fmaf(q1.w, K0[7], d);
            d = fmaf(q2.x, K0[8], d);  d = fmaf(q2.y, K0[9], d);
            d = fmaf(q2.z, K0[10], d); d = fmaf(q2.w, K0[11], d);
            d = fmaf(q3.x, K0[12], d); d = fmaf(q3.y, K0[13], d);
            d = fmaf(q3.z, K0[14], d); d = fmaf(q3.w, K0[15], d);
            Ssm[r * SST + jgl] += d;
        }
    }
    __syncthreads();

    // ---- P2: softmax; read S (strided scalar, conflict-free), write Pt(257)
    {
#pragma unroll
        for (int rr = 0; rr < 2; rr++) {
            const int r = warp * 2 + rr;
            float v[8];
#pragma unroll
            for (int m = 0; m < 8; m++) v[m] = Ssm[r * SST + lane + 32 * m];
            float mx = v[0];
#pragma unroll
            for (int m = 1; m < 8; m++) mx = fmaxf(mx, v[m]);
#pragma unroll
            for (int o = 16; o > 0; o >>= 1) mx = fmaxf(mx, __shfl_xor_sync(0xffffffffu, mx, o));
            float s = 0.f;
#pragma unroll
            for (int m = 0; m < 8; m++) { v[m] = __expf(v[m] - mx); s += v[m]; }
#pragma unroll
            for (int o = 16; o > 0; o >>= 1) s += __shfl_xor_sync(0xffffffffu, s, o);
            float inv = 1.f / s;
#pragma unroll
            for (int m = 0; m < 8; m++) Pt[r * PTS + lane + 32 * m] = v[m] * inv;
        }
    }
    __syncthreads();   // S now dead -> region becomes red

    // ---- P3: AV. warp = 16-j group; lane = row. p from Pt conflict-free.
    {
        const int j0 = warp * 16;
        float acc[16];
#pragma unroll
        for (int v = 0; v < 16; v++) acc[v] = 0.f;
#pragma unroll
        for (int jj = 0; jj < 16; jj++) {
            const int j = j0 + jj;
            float p = Pt[lane * PTS + j];                      // conflict-free
            const float4* vp = (const float4*)(sV + j * 16);   // broadcast
            float4 v0 = vp[0], v1 = vp[1], v2 = vp[2], v3 = vp[3];
            acc[0]  = fmaf(p, v0.x, acc[0]);  acc[1]  = fmaf(p, v0.y, acc[1]);
            acc[2]  = fmaf(p, v0.z, acc[2]);  acc[3]  = fmaf(p, v0.w, acc[3]);
            acc[4]  = fmaf(p, v1.x, acc[4]);  acc[5]  = fmaf(p, v1.y, acc[5]);
            acc[6]  = fmaf(p, v1.z, acc[6]);  acc[7]  = fmaf(p, v1.w, acc[7]);
            acc[8]  = fmaf(p, v2.x, acc[8]);  acc[9]  = fmaf(p, v2.y, acc[9]);
            acc[10] = fmaf(p, v2.z, acc[10]); acc[11] = fmaf(p, v2.w, acc[11]);
            acc[12] = fmaf(p, v3.x, acc[12]); acc[13] = fmaf(p, v3.y, acc[13]);
            acc[14] = fmaf(p, v3.z, acc[14]); acc[15] = fmaf(p, v3.w, acc[15]);
        }
        float* rp = red + (warp * 32 + lane) * RST;
#pragma unroll
        for (int v = 0; v < 16; v++) rp[v] = acc[v];          // conflict-free (stride 17)
    }
    __syncthreads();

    // ---- P4: sum 16 j-group partials, write g_heads
    {
        const int r = tid >> 4, v = tid & 15;
        float s = 0.f;
#pragma unroll
        for (int jq = 0; jq < 16; jq++)
            s += red[(jq * 32 + r) * RST + v];
        g_heads[(size_t)(b * NN + itile + r) * HK + head * 16 + v] = s;
    }
}

// =====================================================================
// host launcher
// =====================================================================
extern "C" void kernel_launch(void* const* d_in, const int* in_sizes, int n_in,
                              void* d_out, int out_size)
{
    (void)in_sizes; (void)n_in; (void)out_size;
    const float* q    = (const float*)d_in[0];
    const float* hx   = (const float*)d_in[1];
    const int*   mask = (const int*)d_in[2];
    const float* edge = (const float*)d_in[3];
    const float* Wq   = (const float*)d_in[4];
    const float* Wk   = (const float*)d_in[5];
    const float* Wv   = (const float*)d_in[6];
    const float* Wo   = (const float*)d_in[7];
    const float* mw1  = (const float*)d_in[8];
    const float* mb1  = (const float*)d_in[9];
    const float* mw2  = (const float*)d_in[10];
    const float* mb2  = (const float*)d_in[11];
    const float* mw3  = (const float*)d_in[12];
    const float* mb3  = (const float*)d_in[13];

    const int smem_gemm = (128 * 128 + 64 * AS) * 4;
    const int smem_attn = 22144 * 4;   // 88,576 B

    cudaFuncSetAttribute(gemm_qkv_kernel,   cudaFuncAttributeMaxDynamicSharedMemorySize, smem_gemm);
    cudaFuncSetAttribute(gemm_out_kernel,   cudaFuncAttributeMaxDynamicSharedMemorySize, smem_gemm);
    cudaFuncSetAttribute(attn_fused_kernel, cudaFuncAttributeMaxDynamicSharedMemorySize, smem_attn);

    pwl_build_kernel<<<1, 512>>>(mw1, mb1, mw2, mb2, mw3, mb3);

    gemm_qkv_kernel<<<dim3(ROWS / 64, 3), 256, smem_gemm>>>(q, hx, Wq, Wk, Wv);

    seg_kernel<<<(BB * NN * NN) / (512 * 4), 512>>>(edge, mask);

    attn_fused_kernel<<<dim3(64, BB), 512, smem_attn>>>(edge);

    gemm_out_kernel<<<ROWS / 64, 256, smem_gemm>>>(Wo, (float*)d_out);
}